// round 1
// baseline (speedup 1.0000x reference)
#include <cuda_runtime.h>
#include <cstdint>

#define BATCH 8
#define NROI 2000
#define NCLS 81
#define NPAD 2048
#define MAXDET 100
#define NTHREADS 1024
#define META_W (12 + NCLS)

struct SmemLayout {
    float4 box[NROI];                 // refined+clipped boxes (by original roi index)
    float score[NROI];                // class score (by original roi index)
    unsigned long long key[NPAD];     // sort keys: desc(score) | index
    int keep[NROI];                   // keep flags (by sorted position)
    unsigned char cls[NROI];          // class id (by original roi index)
    int list[MAXDET];                 // selected original indices, in output order
    int Mcnt;                         // number of valid (prefix of sorted order)
    int selcnt;
    float win[4];
};

__global__ __launch_bounds__(NTHREADS, 1)
void DetectionLayer_kernel(const float* __restrict__ rois,
                           const float* __restrict__ probs,
                           const float* __restrict__ deltas,
                           const float* __restrict__ meta,
                           float* __restrict__ out) {
    extern __shared__ unsigned char smraw[];
    SmemLayout& sm = *reinterpret_cast<SmemLayout*>(smraw);

    const int b = blockIdx.x;
    const int tid = threadIdx.x;
    const int lane = tid & 31;
    const int warp = tid >> 5;
    const int NW = NTHREADS / 32;

    if (tid == 0) {
        // window = (meta[b,7:11] - [0,0,1,1]) / ([h,w,h,w]-1), h/w from meta row 0
        float h = meta[4], w = meta[5];
        float sy = h - 1.0f, sx = w - 1.0f;
        const float* mw = meta + (size_t)b * META_W + 7;
        sm.win[0] = mw[0] / sy;
        sm.win[1] = mw[1] / sx;
        sm.win[2] = (mw[2] - 1.0f) / sy;
        sm.win[3] = (mw[3] - 1.0f) / sx;
        sm.Mcnt = NROI;
        sm.selcnt = 0;
    }
    __syncthreads();
    const float wy1 = sm.win[0], wx1 = sm.win[1], wy2 = sm.win[2], wx2 = sm.win[3];

    // ---------------- Phase A: per-ROI argmax + delta refine + clip -----------
    const float* pb = probs  + (size_t)b * NROI * NCLS;
    const float* db = deltas + (size_t)b * NROI * NCLS * 4;
    const float* rb = rois   + (size_t)b * NROI * 4;

    for (int r = warp; r < NROI; r += NW) {
        const float* p = pb + (size_t)r * NCLS;
        // lanes cover columns lane, lane+32, lane+64 (<81). First-occurrence argmax.
        float v = p[lane];
        int ci = lane;
        {
            float v2 = p[lane + 32];
            if (v2 > v) { v = v2; ci = lane + 32; }
            if (lane + 64 < NCLS) {
                float v3 = p[lane + 64];
                if (v3 > v) { v = v3; ci = lane + 64; }
            }
        }
#pragma unroll
        for (int off = 16; off; off >>= 1) {
            float ov = __shfl_down_sync(0xffffffffu, v, off);
            int   oi = __shfl_down_sync(0xffffffffu, ci, off);
            if (ov > v || (ov == v && oi < ci)) { v = ov; ci = oi; }
        }
        if (lane == 0) {
            float4 roi = *reinterpret_cast<const float4*>(rb + (size_t)r * 4);
            float4 d   = *reinterpret_cast<const float4*>(db + ((size_t)r * NCLS + ci) * 4);
            d.x *= 0.1f; d.y *= 0.1f; d.z *= 0.2f; d.w *= 0.2f;
            float hh = roi.z - roi.x;
            float ww = roi.w - roi.y;
            float cy = roi.x + 0.5f * hh + d.x * hh;
            float cx = roi.y + 0.5f * ww + d.y * ww;
            hh *= expf(d.z);
            ww *= expf(d.w);
            float y1 = cy - 0.5f * hh;
            float x1 = cx - 0.5f * ww;
            float y2 = y1 + hh;
            float x2 = x1 + ww;
            y1 = fminf(fmaxf(y1, wy1), wy2);
            x1 = fminf(fmaxf(x1, wx1), wx2);
            y2 = fminf(fmaxf(y2, wy1), wy2);
            x2 = fminf(fmaxf(x2, wx1), wx2);
            sm.box[r]   = make_float4(y1, x1, y2, x2);
            sm.score[r] = v;
            sm.cls[r]   = (unsigned char)ci;
        }
    }
    __syncthreads();

    // ---------------- Phase B: build keys + bitonic sort (2048) ---------------
    for (int t = tid; t < NPAD; t += NTHREADS) {
        unsigned long long k;
        if (t < NROI) {
            float s = sm.score[t];
            bool valid = (sm.cls[t] > 0) && (s >= 0.7f);
            float ss = valid ? s : -1.0f;
            unsigned int u = __float_as_uint(ss);
            u = (u & 0x80000000u) ? ~u : (u | 0x80000000u);   // orderable ascending
            unsigned int desc = ~u;                            // orderable descending
            k = (((unsigned long long)desc) << 32) | (unsigned int)t;
        } else {
            k = 0xFFFFFFFFFFFFFFFFull;
        }
        sm.key[t] = k;
    }
    __syncthreads();

    for (int k2 = 2; k2 <= NPAD; k2 <<= 1) {
        for (int j = k2 >> 1; j > 0; j >>= 1) {
#pragma unroll
            for (int pass = 0; pass < NPAD / NTHREADS; ++pass) {
                int i = tid + pass * NTHREADS;
                int ixj = i ^ j;
                if (ixj > i) {
                    unsigned long long a = sm.key[i];
                    unsigned long long c2 = sm.key[ixj];
                    bool up = ((i & k2) == 0);
                    if ((a > c2) == up) { sm.key[i] = c2; sm.key[ixj] = a; }
                }
            }
            __syncthreads();
        }
    }

    // ---------------- Phase C: keep flags + M (valid prefix length) -----------
    for (int t = tid; t < NROI; t += NTHREADS) {
        int idx = (int)(unsigned int)sm.key[t];
        float s = sm.score[idx];
        bool valid = (sm.cls[idx] > 0) && (s >= 0.7f);
        sm.keep[t] = valid ? 1 : 0;
        if (!valid) atomicMin(&sm.Mcnt, t);
    }
    __syncthreads();
    const int M = sm.Mcnt;

    // ---------------- Phase D: greedy NMS (class-offset => same-class only) ---
    for (int i = 0; i < M; ++i) {
        if (sm.keep[i]) {
            int idxi = (int)(unsigned int)sm.key[i];
            float4 bi = sm.box[idxi];
            int ci = sm.cls[idxi];
            float areai = (bi.z - bi.x) * (bi.w - bi.y);
            for (int j = i + 1 + tid; j < M; j += NTHREADS) {
                if (!sm.keep[j]) continue;
                int idxj = (int)(unsigned int)sm.key[j];
                if ((int)sm.cls[idxj] != ci) continue;   // different class: IoU==0 by offset
                float4 bj = sm.box[idxj];
                float ih = fminf(bi.z, bj.z) - fmaxf(bi.x, bj.x);
                float iw = fminf(bi.w, bj.w) - fmaxf(bi.y, bj.y);
                ih = fmaxf(ih, 0.0f);
                iw = fmaxf(iw, 0.0f);
                float inter = ih * iw;
                float areaj = (bj.z - bj.x) * (bj.w - bj.y);
                float uni = areai + areaj - inter;
                if (inter / (uni + 1e-8f) > 0.3f) sm.keep[j] = 0;
            }
            __syncthreads();
        }
    }

    // ---------------- Phase E: take first 100 kept (== top_k), emit -----------
    if (tid == 0) {
        int c = 0;
        for (int i = 0; i < M && c < MAXDET; ++i) {
            if (sm.keep[i]) sm.list[c++] = (int)(unsigned int)sm.key[i];
        }
        sm.selcnt = c;
    }
    __syncthreads();
    const int cnt = sm.selcnt;
    float* ob = out + (size_t)b * MAXDET * 6;
    for (int t = tid; t < MAXDET * 6; t += NTHREADS) {
        int row = t / 6;
        int col = t - row * 6;
        float val = 0.0f;
        if (row < cnt) {
            int idx = sm.list[row];
            float4 bx = sm.box[idx];
            switch (col) {
                case 0: val = bx.x; break;
                case 1: val = bx.y; break;
                case 2: val = bx.z; break;
                case 3: val = bx.w; break;
                case 4: val = (float)sm.cls[idx]; break;
                default: val = sm.score[idx]; break;
            }
        }
        ob[t] = val;
    }
}

extern "C" void kernel_launch(void* const* d_in, const int* in_sizes, int n_in,
                              void* d_out, int out_size) {
    const float* rois   = (const float*)d_in[0];
    const float* probs  = (const float*)d_in[1];
    const float* deltas = (const float*)d_in[2];
    const float* meta   = (const float*)d_in[3];
    float* out = (float*)d_out;

    size_t smem = sizeof(SmemLayout);
    cudaFuncSetAttribute(DetectionLayer_kernel,
                         cudaFuncAttributeMaxDynamicSharedMemorySize, (int)smem);
    DetectionLayer_kernel<<<BATCH, NTHREADS, smem>>>(rois, probs, deltas, meta, out);
}

// round 2
// speedup vs baseline: 4.3052x; 4.3052x over previous
#include <cuda_runtime.h>
#include <cstdint>

#define BATCH 8
#define NROI 2000
#define NCLS 81
#define NPAD 2048
#define MAXDET 100
#define NTHREADS 1024
#define META_W (12 + NCLS)

struct SmemLayout {
    float4 box[NROI];                 // refined+clipped boxes (by original roi index)
    float4 sbox[NPAD];                // boxes by sorted position
    float score[NROI];                // class score (by original roi index)
    unsigned long long key[NPAD];     // sort keys
    int sidx[NPAD];                   // sorted position -> original index
    int keep[NPAD];                   // keep flags (by sorted position)
    unsigned char cls[NROI];          // class id (by original roi index)
    int segS[256];                    // class segment start (sorted positions)
    int segE[256];                    // class segment end
    float win[4];
};

__device__ __forceinline__ unsigned int f2ord(float s) {
    unsigned int u = __float_as_uint(s);
    return (u & 0x80000000u) ? ~u : (u | 0x80000000u);   // ascending-orderable
}

__global__ __launch_bounds__(NTHREADS, 1)
void DetectionLayer_kernel(const float* __restrict__ rois,
                           const float* __restrict__ probs,
                           const float* __restrict__ deltas,
                           const float* __restrict__ meta,
                           float* __restrict__ out) {
    extern __shared__ unsigned char smraw[];
    SmemLayout& sm = *reinterpret_cast<SmemLayout*>(smraw);

    const int b = blockIdx.x;
    const int tid = threadIdx.x;
    const int lane = tid & 31;
    const int warp = tid >> 5;
    const int NW = NTHREADS / 32;

    if (tid < 256) { sm.segS[tid] = 0; sm.segE[tid] = 0; }
    if (tid == 0) {
        float h = meta[4], w = meta[5];
        float sy = h - 1.0f, sx = w - 1.0f;
        const float* mw = meta + (size_t)b * META_W + 7;
        sm.win[0] = mw[0] / sy;
        sm.win[1] = mw[1] / sx;
        sm.win[2] = (mw[2] - 1.0f) / sy;
        sm.win[3] = (mw[3] - 1.0f) / sx;
    }
    __syncthreads();
    const float wy1 = sm.win[0], wx1 = sm.win[1], wy2 = sm.win[2], wx2 = sm.win[3];

    // ---------------- Phase A: per-ROI argmax + delta refine + clip -----------
    const float* pb = probs  + (size_t)b * NROI * NCLS;
    const float* db = deltas + (size_t)b * NROI * NCLS * 4;
    const float* rb = rois   + (size_t)b * NROI * 4;

    for (int r = warp; r < NROI; r += NW) {
        const float* p = pb + (size_t)r * NCLS;
        float v = p[lane];
        int ci = lane;
        {
            float v2 = p[lane + 32];
            if (v2 > v) { v = v2; ci = lane + 32; }
            if (lane + 64 < NCLS) {
                float v3 = p[lane + 64];
                if (v3 > v) { v = v3; ci = lane + 64; }
            }
        }
#pragma unroll
        for (int off = 16; off; off >>= 1) {
            float ov = __shfl_down_sync(0xffffffffu, v, off);
            int   oi = __shfl_down_sync(0xffffffffu, ci, off);
            if (ov > v || (ov == v && oi < ci)) { v = ov; ci = oi; }
        }
        if (lane == 0) {
            float4 roi = *reinterpret_cast<const float4*>(rb + (size_t)r * 4);
            float4 d   = *reinterpret_cast<const float4*>(db + ((size_t)r * NCLS + ci) * 4);
            d.x *= 0.1f; d.y *= 0.1f; d.z *= 0.2f; d.w *= 0.2f;
            float hh = roi.z - roi.x;
            float ww = roi.w - roi.y;
            float cy = roi.x + 0.5f * hh + d.x * hh;
            float cx = roi.y + 0.5f * ww + d.y * ww;
            hh *= expf(d.z);
            ww *= expf(d.w);
            float y1 = cy - 0.5f * hh;
            float x1 = cx - 0.5f * ww;
            float y2 = y1 + hh;
            float x2 = x1 + ww;
            y1 = fminf(fmaxf(y1, wy1), wy2);
            x1 = fminf(fmaxf(x1, wx1), wx2);
            y2 = fminf(fmaxf(y2, wy1), wy2);
            x2 = fminf(fmaxf(x2, wx1), wx2);
            sm.box[r]   = make_float4(y1, x1, y2, x2);
            sm.score[r] = v;
            sm.cls[r]   = (unsigned char)ci;
        }
    }
    __syncthreads();

    // ------------- Phase B: sort #1 by (class asc, score desc, idx asc) -------
    // key = [8b class | 32b desc-orderable(score) | 11b idx]; invalid -> class 255
    for (int t = tid; t < NPAD; t += NTHREADS) {
        unsigned long long k;
        if (t < NROI) {
            float s = sm.score[t];
            int c = sm.cls[t];
            bool valid = (c > 0) && (s >= 0.7f);
            unsigned long long cb = valid ? (unsigned long long)c : 255ull;
            unsigned int desc = ~f2ord(s);
            k = (cb << 43) | (((unsigned long long)desc) << 11) | (unsigned int)t;
        } else {
            k = 0xFFFFFFFFFFFFFFFFull;
        }
        sm.key[t] = k;
    }
    __syncthreads();

    // bitonic sort of 2048 keys; j<32 stages stay in-warp (syncwarp only)
    for (int k2 = 2; k2 <= NPAD; k2 <<= 1) {
        int j = k2 >> 1;
        for (; j >= 32; j >>= 1) {
#pragma unroll
            for (int pass = 0; pass < NPAD / NTHREADS; ++pass) {
                int i = tid + pass * NTHREADS;
                int ixj = i ^ j;
                if (ixj > i) {
                    unsigned long long a = sm.key[i];
                    unsigned long long c2 = sm.key[ixj];
                    bool up = ((i & k2) == 0);
                    if ((a > c2) == up) { sm.key[i] = c2; sm.key[ixj] = a; }
                }
            }
            __syncthreads();
        }
        for (; j > 0; j >>= 1) {
#pragma unroll
            for (int pass = 0; pass < NPAD / NTHREADS; ++pass) {
                int i = tid + pass * NTHREADS;
                int ixj = i ^ j;
                if (ixj > i) {
                    unsigned long long a = sm.key[i];
                    unsigned long long c2 = sm.key[ixj];
                    bool up = ((i & k2) == 0);
                    if ((a > c2) == up) { sm.key[i] = c2; sm.key[ixj] = a; }
                }
            }
            __syncwarp();
        }
        __syncthreads();
    }

    // ------------- Phase C: segment boundaries + sorted-order copies ----------
    for (int t = tid; t < NPAD; t += NTHREADS) {
        if (t < NROI) {
            unsigned long long k = sm.key[t];
            int idx = (int)(k & 0x7FFu);
            int c   = (int)(k >> 43);
            sm.sidx[t] = idx;
            sm.sbox[t] = sm.box[idx];
            sm.keep[t] = (c <= 80) ? 1 : 0;
            int cp = (t == 0) ? -1 : (int)(sm.key[t - 1] >> 43);
            if (c != cp && c <= 80) sm.segS[c] = t;
            int cn = (t == NROI - 1) ? -1 : (int)(sm.key[t + 1] >> 43);
            if (c != cn && c <= 80) sm.segE[c] = t + 1;
        } else {
            sm.keep[t] = 0;
        }
    }
    __syncthreads();

    // ------------- Phase D: per-class greedy NMS, one warp per class ----------
    for (int c = 1 + warp; c <= 80; c += NW) {
        int s = sm.segS[c];
        int e = sm.segE[c];
        for (int i = s; i < e; ++i) {
            if (sm.keep[i]) {
                float4 bi = sm.sbox[i];
                float areai = (bi.z - bi.x) * (bi.w - bi.y);
                for (int j = i + 1 + lane; j < e; j += 32) {
                    if (!sm.keep[j]) continue;
                    float4 bj = sm.sbox[j];
                    float ih = fmaxf(fminf(bi.z, bj.z) - fmaxf(bi.x, bj.x), 0.0f);
                    float iw = fmaxf(fminf(bi.w, bj.w) - fmaxf(bi.y, bj.y), 0.0f);
                    float inter = ih * iw;
                    float areaj = (bj.z - bj.x) * (bj.w - bj.y);
                    float uni = areai + areaj - inter;
                    if (inter / (uni + 1e-8f) > 0.3f) sm.keep[j] = 0;
                }
                __syncwarp();
            }
        }
    }
    __syncthreads();

    // ------------- Phase E: sort #2 by (kept-score desc, sorted-pos asc) ------
    for (int t = tid; t < NPAD; t += NTHREADS) {
        float s = -1.0f;
        if (t < NROI && sm.keep[t]) s = sm.score[sm.sidx[t]];
        unsigned int desc = ~f2ord(s);
        sm.key[t] = (((unsigned long long)desc) << 11) | (unsigned int)t;
    }
    __syncthreads();

    for (int k2 = 2; k2 <= NPAD; k2 <<= 1) {
        int j = k2 >> 1;
        for (; j >= 32; j >>= 1) {
#pragma unroll
            for (int pass = 0; pass < NPAD / NTHREADS; ++pass) {
                int i = tid + pass * NTHREADS;
                int ixj = i ^ j;
                if (ixj > i) {
                    unsigned long long a = sm.key[i];
                    unsigned long long c2 = sm.key[ixj];
                    bool up = ((i & k2) == 0);
                    if ((a > c2) == up) { sm.key[i] = c2; sm.key[ixj] = a; }
                }
            }
            __syncthreads();
        }
        for (; j > 0; j >>= 1) {
#pragma unroll
            for (int pass = 0; pass < NPAD / NTHREADS; ++pass) {
                int i = tid + pass * NTHREADS;
                int ixj = i ^ j;
                if (ixj > i) {
                    unsigned long long a = sm.key[i];
                    unsigned long long c2 = sm.key[ixj];
                    bool up = ((i & k2) == 0);
                    if ((a > c2) == up) { sm.key[i] = c2; sm.key[ixj] = a; }
                }
            }
            __syncwarp();
        }
        __syncthreads();
    }

    // ------------- Phase F: emit top-100 ---------------------------------------
    float* ob = out + (size_t)b * MAXDET * 6;
    for (int t = tid; t < MAXDET * 6; t += NTHREADS) {
        int row = t / 6;
        int col = t - row * 6;
        unsigned long long k = sm.key[row];
        unsigned int desc = (unsigned int)(k >> 11);
        unsigned int o = ~desc;
        unsigned int u = (o & 0x80000000u) ? (o ^ 0x80000000u) : ~o;
        float s = __uint_as_float(u);
        float val = 0.0f;
        if (s >= 0.0f) {
            int sp  = (int)(k & 0x7FFu);
            int idx = sm.sidx[sp];
            float4 bx = sm.box[idx];
            switch (col) {
                case 0: val = bx.x; break;
                case 1: val = bx.y; break;
                case 2: val = bx.z; break;
                case 3: val = bx.w; break;
                case 4: val = (float)sm.cls[idx]; break;
                default: val = sm.score[idx]; break;
            }
        }
        ob[t] = val;
    }
}

extern "C" void kernel_launch(void* const* d_in, const int* in_sizes, int n_in,
                              void* d_out, int out_size) {
    const float* rois   = (const float*)d_in[0];
    const float* probs  = (const float*)d_in[1];
    const float* deltas = (const float*)d_in[2];
    const float* meta   = (const float*)d_in[3];
    float* out = (float*)d_out;

    size_t smem = sizeof(SmemLayout);
    cudaFuncSetAttribute(DetectionLayer_kernel,
                         cudaFuncAttributeMaxDynamicSharedMemorySize, (int)smem);
    DetectionLayer_kernel<<<BATCH, NTHREADS, smem>>>(rois, probs, deltas, meta, out);
}

// round 3
// speedup vs baseline: 7.7854x; 1.8084x over previous
#include <cuda_runtime.h>
#include <cstdint>

#define BATCH 8
#define NROI 2000
#define NCLS 81
#define NPAD 2048
#define MAXDET 100
#define META_W (12 + NCLS)
#define K2_THREADS 1024
#define ROIS_PER_BLK 8

// ---------------- device scratch (no allocations allowed) -------------------
__device__ float4             g_box[BATCH][NPAD];
__device__ float              g_score[BATCH][NPAD];
__device__ int                g_cls[BATCH][NPAD];
__device__ unsigned long long g_key[BATCH][NPAD];

__device__ __forceinline__ unsigned int f2ord(float s) {
    unsigned int u = __float_as_uint(s);
    return (u & 0x80000000u) ? ~u : (u | 0x80000000u);   // ascending-orderable
}

// ============================= Kernel 1 ======================================
// One warp per ROI: argmax over 81 classes, delta refine, clip, key build.
__global__ __launch_bounds__(ROIS_PER_BLK * 32)
void refine_kernel(const float* __restrict__ rois,
                   const float* __restrict__ probs,
                   const float* __restrict__ deltas,
                   const float* __restrict__ meta) {
    const int blk   = blockIdx.x;
    const int b     = blk / (NROI / ROIS_PER_BLK);
    const int rblk  = blk % (NROI / ROIS_PER_BLK);
    const int warp  = threadIdx.x >> 5;
    const int lane  = threadIdx.x & 31;
    const int r     = rblk * ROIS_PER_BLK + warp;

    const float* p = probs + ((size_t)b * NROI + r) * NCLS;
    float v = p[lane];
    int ci = lane;
    {
        float v2 = p[lane + 32];
        if (v2 > v) { v = v2; ci = lane + 32; }
        if (lane + 64 < NCLS) {
            float v3 = p[lane + 64];
            if (v3 > v) { v = v3; ci = lane + 64; }
        }
    }
#pragma unroll
    for (int off = 16; off; off >>= 1) {
        float ov = __shfl_down_sync(0xffffffffu, v, off);
        int   oi = __shfl_down_sync(0xffffffffu, ci, off);
        if (ov > v || (ov == v && oi < ci)) { v = ov; ci = oi; }
    }
    if (lane == 0) {
        // window
        float h = meta[4], w = meta[5];
        float sy = h - 1.0f, sx = w - 1.0f;
        const float* mw = meta + (size_t)b * META_W + 7;
        float wy1 = mw[0] / sy;
        float wx1 = mw[1] / sx;
        float wy2 = (mw[2] - 1.0f) / sy;
        float wx2 = (mw[3] - 1.0f) / sx;

        float4 roi = *reinterpret_cast<const float4*>(rois + ((size_t)b * NROI + r) * 4);
        float4 d   = *reinterpret_cast<const float4*>(deltas + (((size_t)b * NROI + r) * NCLS + ci) * 4);
        d.x *= 0.1f; d.y *= 0.1f; d.z *= 0.2f; d.w *= 0.2f;
        float hh = roi.z - roi.x;
        float ww = roi.w - roi.y;
        float cy = roi.x + 0.5f * hh + d.x * hh;
        float cx = roi.y + 0.5f * ww + d.y * ww;
        hh *= expf(d.z);
        ww *= expf(d.w);
        float y1 = cy - 0.5f * hh;
        float x1 = cx - 0.5f * ww;
        float y2 = y1 + hh;
        float x2 = x1 + ww;
        y1 = fminf(fmaxf(y1, wy1), wy2);
        x1 = fminf(fmaxf(x1, wx1), wx2);
        y2 = fminf(fmaxf(y2, wy1), wy2);
        x2 = fminf(fmaxf(x2, wx1), wx2);

        g_box[b][r]   = make_float4(y1, x1, y2, x2);
        g_score[b][r] = v;
        g_cls[b][r]   = ci;
        bool valid = (ci > 0) && (v >= 0.7f);
        unsigned long long k;
        if (valid) {
            unsigned int desc = ~f2ord(v);
            k = (((unsigned long long)desc) << 11) | (unsigned int)r;
        } else {
            k = 0xFFFFFFFFFFFFFFFFull;
        }
        g_key[b][r] = k;
    }
}

// ============================= Kernel 2 ======================================
struct Sm2 {
    unsigned long long key[NPAD];   // sort keys (score desc | idx)
    float4 sbox[NPAD];              // box by sorted pos
    float  sscore[NPAD];            // score by sorted pos
    unsigned short sidx[NPAD];      // sorted pos -> original idx
    unsigned char scls[NPAD];       // class by sorted pos
    unsigned char keep[NPAD];       // keep flag by sorted pos
    unsigned short list[NPAD];      // per-class ordered sorted-positions
    int cnt[NCLS + 1];              // per-class count
    int off[NCLS + 1];              // per-class list offset
    int sel[MAXDET];                // selected sorted positions
    int selcnt;
    int Mcnt;                       // number of valid (prefix of sorted order)
};

__global__ __launch_bounds__(K2_THREADS, 1)
void nms_kernel(float* __restrict__ out) {
    extern __shared__ unsigned char smraw[];
    Sm2& sm = *reinterpret_cast<Sm2*>(smraw);

    const int b = blockIdx.x;
    const int tid = threadIdx.x;
    const int lane = tid & 31;
    const int warp = tid >> 5;
    const unsigned lmask = (1u << lane) - 1u;

    if (tid <= NCLS) { sm.cnt[tid] = 0; }
    if (tid == 0) { sm.selcnt = 0; sm.Mcnt = NROI; }
    // load keys
    for (int t = tid; t < NPAD; t += K2_THREADS)
        sm.key[t] = (t < NROI) ? g_key[b][t] : 0xFFFFFFFFFFFFFFFFull;
    __syncthreads();

    // ---- bitonic sort of 2048 keys (score desc primary) ----
    for (int k2 = 2; k2 <= NPAD; k2 <<= 1) {
        int j = k2 >> 1;
        for (; j >= 32; j >>= 1) {
#pragma unroll
            for (int pass = 0; pass < NPAD / K2_THREADS; ++pass) {
                int i = tid + pass * K2_THREADS;
                int ixj = i ^ j;
                if (ixj > i) {
                    unsigned long long a = sm.key[i];
                    unsigned long long c2 = sm.key[ixj];
                    bool up = ((i & k2) == 0);
                    if ((a > c2) == up) { sm.key[i] = c2; sm.key[ixj] = a; }
                }
            }
            __syncthreads();
        }
        for (; j > 0; j >>= 1) {
#pragma unroll
            for (int pass = 0; pass < NPAD / K2_THREADS; ++pass) {
                int i = tid + pass * K2_THREADS;
                int ixj = i ^ j;
                if (ixj > i) {
                    unsigned long long a = sm.key[i];
                    unsigned long long c2 = sm.key[ixj];
                    bool up = ((i & k2) == 0);
                    if ((a > c2) == up) { sm.key[i] = c2; sm.key[ixj] = a; }
                }
            }
            __syncwarp();
        }
        __syncthreads();
    }

    // ---- gather sorted-order data, histogram classes ----
    for (int t = tid; t < NPAD; t += K2_THREADS) {
        unsigned long long k = sm.key[t];
        if (t < NROI && k != 0xFFFFFFFFFFFFFFFFull) {
            int idx = (int)(k & 0x7FFu);
            int c = g_cls[b][idx];
            sm.sidx[t] = (unsigned short)idx;
            sm.scls[t] = (unsigned char)c;
            sm.sbox[t] = g_box[b][idx];
            sm.sscore[t] = g_score[b][idx];
            sm.keep[t] = 1;
            atomicAdd(&sm.cnt[c], 1);
        } else {
            sm.keep[t] = 0;
            sm.scls[t] = 0;
            if (t < NROI) atomicMin(&sm.Mcnt, t);
        }
    }
    __syncthreads();
    const int M = sm.Mcnt;

    // ---- per-class offsets (serial over 81, trivial) ----
    if (tid == 0) {
        int acc = 0;
        for (int c = 1; c <= NCLS - 1 + 1 && c <= NCLS; ++c) { }
        for (int c = 1; c < NCLS; ++c) { sm.off[c] = acc; acc += sm.cnt[c]; }
    }
    __syncthreads();

    // ---- build per-class ordered lists via warp ballot scans ----
    for (int c = 1 + warp; c < NCLS; c += K2_THREADS / 32) {
        int base = sm.off[c];
        int acc = 0;
        int n = sm.cnt[c];
        for (int t0 = 0; t0 < M && acc < n; t0 += 32) {
            int t = t0 + lane;
            bool mine = (t < M) && (sm.scls[t] == (unsigned char)c) && (sm.keep[t] != 0);
            unsigned mball = __ballot_sync(0xffffffffu, mine);
            if (mine) sm.list[base + acc + __popc(mball & lmask)] = (unsigned short)t;
            acc += __popc(mball);
        }
    }
    __syncthreads();

    // ---- per-class greedy NMS, one warp per class ----
    for (int c = 1 + warp; c < NCLS; c += K2_THREADS / 32) {
        int base = sm.off[c];
        int n = sm.cnt[c];
        for (int i = 0; i < n; ++i) {
            int ti = sm.list[base + i];
            if (sm.keep[ti]) {
                float4 bi = sm.sbox[ti];
                float areai = (bi.z - bi.x) * (bi.w - bi.y);
                for (int j = i + 1 + lane; j < n; j += 32) {
                    int tj = sm.list[base + j];
                    if (!sm.keep[tj]) continue;
                    float4 bj = sm.sbox[tj];
                    float ih = fmaxf(fminf(bi.z, bj.z) - fmaxf(bi.x, bj.x), 0.0f);
                    float iw = fmaxf(fminf(bi.w, bj.w) - fmaxf(bi.y, bj.y), 0.0f);
                    float inter = ih * iw;
                    float areaj = (bj.z - bj.x) * (bj.w - bj.y);
                    float uni = areai + areaj - inter;
                    if (inter / (uni + 1e-8f) > 0.3f) sm.keep[tj] = 0;
                }
                __syncwarp();
            }
        }
    }
    __syncthreads();

    // ---- first 100 kept in sorted (score desc) order ----
    if (warp == 0) {
        int cnt = 0;
        for (int t0 = 0; t0 < M && cnt < MAXDET; t0 += 32) {
            int t = t0 + lane;
            bool k = (t < M) && (sm.keep[t] != 0);
            unsigned mball = __ballot_sync(0xffffffffu, k);
            int p = cnt + __popc(mball & lmask);
            if (k && p < MAXDET) sm.sel[p] = t;
            cnt += __popc(mball);
        }
        if (lane == 0) sm.selcnt = (cnt < MAXDET) ? cnt : MAXDET;
    }
    __syncthreads();

    // ---- emit ----
    const int cnt = sm.selcnt;
    float* ob = out + (size_t)b * MAXDET * 6;
    for (int t = tid; t < MAXDET * 6; t += K2_THREADS) {
        int row = t / 6;
        int col = t - row * 6;
        float val = 0.0f;
        if (row < cnt) {
            int sp = sm.sel[row];
            float4 bx = sm.sbox[sp];
            switch (col) {
                case 0: val = bx.x; break;
                case 1: val = bx.y; break;
                case 2: val = bx.z; break;
                case 3: val = bx.w; break;
                case 4: val = (float)sm.scls[sp]; break;
                default: val = sm.sscore[sp]; break;
            }
        }
        ob[t] = val;
    }
}

extern "C" void kernel_launch(void* const* d_in, const int* in_sizes, int n_in,
                              void* d_out, int out_size) {
    const float* rois   = (const float*)d_in[0];
    const float* probs  = (const float*)d_in[1];
    const float* deltas = (const float*)d_in[2];
    const float* meta   = (const float*)d_in[3];
    float* out = (float*)d_out;

    refine_kernel<<<BATCH * (NROI / ROIS_PER_BLK), ROIS_PER_BLK * 32>>>(rois, probs, deltas, meta);

    size_t smem = sizeof(Sm2);
    cudaFuncSetAttribute(nms_kernel,
                         cudaFuncAttributeMaxDynamicSharedMemorySize, (int)smem);
    nms_kernel<<<BATCH, K2_THREADS, smem>>>(out);
}